// round 6
// baseline (speedup 1.0000x reference)
#include <cuda_runtime.h>
#include <cstdint>

// Problem constants (B=64, C=512, H=W=28, G=8)
#define HWN    784       // H*W
#define HW4    196       // HW/4
#define CPG    64        // channels per group
#define NBG    512       // B*G tiles
#define EPS    1e-5f
#define NTHR   256       // 8 warps
#define SLICE  98        // HWN / 8 warps

#define CSTG     4                   // channels per pipeline stage
#define NSTAGE   16                  // CPG / CSTG
#define NSLOT    4                   // ring depth
#define STG_FLOATS (CSTG * HWN)      // 3136
#define STG_BYTES  (STG_FLOATS * 4)  // 12544

// smem layout (floats):
//   ring:   NSLOT * STG_FLOATS = 12544
//   s/gate: HWN = 784
//   means:  NSLOT*CSTG = 16
//   red:    20
//   mbar:   8 (4 x u64)
#define OFF_S     (NSLOT * STG_FLOATS)
#define OFF_MEANS (OFF_S + HWN)
#define OFF_RED   (OFF_MEANS + NSLOT * CSTG)
#define OFF_MBAR  (OFF_RED + 20)
#define SMEM_FLOATS (OFF_MBAR + 8)
#define SMEM_BYTES  (SMEM_FLOATS * 4)

__device__ __forceinline__ uint32_t smem_u32(const void* p) {
    uint32_t a;
    asm("{ .reg .u64 t; cvta.to.shared.u64 t, %1; cvt.u32.u64 %0, t; }"
        : "=r"(a) : "l"(p));
    return a;
}

__device__ __forceinline__ void mbar_wait(uint32_t mbar, uint32_t parity) {
    asm volatile(
        "{\n\t"
        ".reg .pred P;\n\t"
        "WL_%=: mbarrier.try_wait.parity.acquire.cta.shared::cta.b64 P, [%0], %1, 0x989680;\n\t"
        "@P bra WD_%=;\n\t"
        "bra WL_%=;\n\t"
        "WD_%=:\n\t"
        "}" :: "r"(mbar), "r"(parity) : "memory");
}

__device__ __forceinline__ void tma_issue(uint32_t mbar, uint32_t dst,
                                          const char* src) {
    asm volatile("mbarrier.arrive.expect_tx.shared::cta.b64 _, [%0], %1;"
                 :: "r"(mbar), "r"((uint32_t)STG_BYTES) : "memory");
    asm volatile(
        "cp.async.bulk.shared::cluster.global.mbarrier::complete_tx::bytes "
        "[%0], [%1], %2, [%3];"
        :: "r"(dst), "l"(src), "r"((uint32_t)STG_BYTES), "r"(mbar)
        : "memory");
}

__global__ __launch_bounds__(NTHR, 4)
void simam_stream_kernel(const float* __restrict__ x,
                         const float* __restrict__ weight,
                         const float* __restrict__ bias,
                         float* __restrict__ out)
{
    extern __shared__ float smem[];
    float*  ring    = smem;
    float*  s_s     = smem + OFF_S;
    float4* s_s4    = (float4*)s_s;
    float*  s_means = smem + OFF_MEANS;
    float*  s_red   = smem + OFF_RED;
    const uint32_t mbar0 = smem_u32(smem + OFF_MBAR);

    const int bg = blockIdx.x;
    const int g  = bg & 7;
    const float* xt = x   + (size_t)bg * (CPG * HWN);
    float*       ot = out + (size_t)bg * (CPG * HWN);

    const int tid  = threadIdx.x;
    const int w    = tid >> 5;
    const int lane = tid & 31;

    // ---- init barriers + prologue: fill the ring ----
    if (tid == 0) {
        #pragma unroll
        for (int i = 0; i < NSLOT; i++)
            asm volatile("mbarrier.init.shared::cta.b64 [%0], 1;"
                         :: "r"(mbar0 + i * 8) : "memory");
    }
    __syncthreads();
    if (tid == 0) {
        const uint32_t ring0 = smem_u32(ring);
        #pragma unroll
        for (int st = 0; st < NSLOT; st++)
            tma_issue(mbar0 + st * 8, ring0 + st * STG_BYTES,
                      (const char*)xt + st * STG_BYTES);
    }

    // ---- pass 1: streamed means + s accumulation ----
    float acc0 = 0.f, acc1 = 0.f, acc2 = 0.f, acc3 = 0.f;  // s slice regs
    const int jb = w * SLICE + lane;                        // slice base index

    for (int st = 0; st < NSTAGE; st++) {
        const int      slot   = st & (NSLOT - 1);
        const uint32_t parity = (st >> 2) & 1;
        mbar_wait(mbar0 + slot * 8, parity);

        float* buf = ring + slot * STG_FLOATS;

        // warps 0..3: per-channel mean of channel (slot,cc=w)
        if (w < CSTG) {
            const float4* row4 = (const float4*)(buf + w * HWN);
            float cs = 0.f;
            #pragma unroll
            for (int k = 0; k < 7; k++) {
                const int j = lane + 32 * k;
                if (j < HW4) {
                    float4 v = row4[j];
                    cs += (v.x + v.y) + (v.z + v.w);
                }
            }
            #pragma unroll
            for (int o = 16; o; o >>= 1) cs += __shfl_xor_sync(0xffffffffu, cs, o);
            if (lane == 0) s_means[slot * CSTG + w] = cs * (1.0f / HWN);
        }
        __syncthreads();

        // all 8 warps: accumulate m_c * x[c, slice] into register slice
        #pragma unroll
        for (int cc = 0; cc < CSTG; cc++) {
            const float  m   = s_means[slot * CSTG + cc];
            const float* row = buf + cc * HWN + jb;
            if (lane + 0  < SLICE) acc0 += m * row[0];
            if (lane + 32 < SLICE) acc1 += m * row[32];
            if (lane + 64 < SLICE) acc2 += m * row[64];
            acc3 += (lane + 96 < SLICE) ? m * row[96] : 0.f;
        }
        __syncthreads();

        // refill this slot with stage st+NSLOT
        const int nx = st + NSLOT;
        if (tid == 0 && nx < NSTAGE) {
            tma_issue(mbar0 + slot * 8,
                      smem_u32(ring) + slot * STG_BYTES,
                      (const char*)xt + nx * STG_BYTES);
        }
    }

    // ---- stats over s: spill slices to smem, reduce sum & sumsq ----
    float lsum = 0.f, lsq = 0.f;
    {
        float* dst = s_s + jb;
        if (lane + 0  < SLICE) { dst[0]  = acc0; lsum += acc0; lsq += acc0 * acc0; }
        if (lane + 32 < SLICE) { dst[32] = acc1; lsum += acc1; lsq += acc1 * acc1; }
        if (lane + 64 < SLICE) { dst[64] = acc2; lsum += acc2; lsq += acc2 * acc2; }
        if (lane + 96 < SLICE) { dst[96] = acc3; lsum += acc3; lsq += acc3 * acc3; }
    }
    #pragma unroll
    for (int o = 16; o; o >>= 1) {
        lsum += __shfl_xor_sync(0xffffffffu, lsum, o);
        lsq  += __shfl_xor_sync(0xffffffffu, lsq,  o);
    }
    if (lane == 0) { s_red[w] = lsum; s_red[8 + w] = lsq; }
    __syncthreads();
    if (tid == 0) {
        float ts = 0.f, tq = 0.f;
        #pragma unroll
        for (int i = 0; i < 8; i++) { ts += s_red[i]; tq += s_red[8 + i]; }
        const float mu  = ts * (1.0f / HWN);
        const float var = tq * (1.0f / HWN) - mu * mu;
        s_red[16] = mu;
        s_red[17] = rsqrtf(var + EPS);
    }
    __syncthreads();

    // ---- gate in place over s ----
    {
        const float mu = s_red[16];
        const float rs = s_red[17];
        const float wg = weight[g];
        const float bb = bias[g];
        if (tid < HW4) {
            float4 sv = s_s4[tid];
            float4 gt;
            gt.x = 1.0f / (1.0f + __expf(-((sv.x - mu) * rs * wg + bb)));
            gt.y = 1.0f / (1.0f + __expf(-((sv.y - mu) * rs * wg + bb)));
            gt.z = 1.0f / (1.0f + __expf(-((sv.z - mu) * rs * wg + bb)));
            gt.w = 1.0f / (1.0f + __expf(-((sv.w - mu) * rs * wg + bb)));
            s_s4[tid] = gt;
        }
    }
    __syncthreads();

    // ---- pass 2: re-read x (L2-hot), multiply by gate, store ----
    for (int c = w; c < CPG; c += 8) {
        const float4* xrow = (const float4*)(xt + c * HWN);
        float4*       orow = (float4*)(ot + c * HWN);
        #pragma unroll
        for (int k = 0; k < 7; k++) {
            const int j = lane + 32 * k;
            if (j < HW4) {
                float4 v  = __ldg(xrow + j);
                float4 gt = s_s4[j];
                v.x *= gt.x; v.y *= gt.y; v.z *= gt.z; v.w *= gt.w;
                orow[j] = v;
            }
        }
    }
}

extern "C" void kernel_launch(void* const* d_in, const int* in_sizes, int n_in,
                              void* d_out, int out_size)
{
    const float* x  = (const float*)d_in[0];
    const float* wt = (const float*)d_in[1];
    const float* bs = (const float*)d_in[2];
    float* out = (float*)d_out;

    cudaFuncSetAttribute(simam_stream_kernel,
                         cudaFuncAttributeMaxDynamicSharedMemorySize, SMEM_BYTES);
    simam_stream_kernel<<<NBG, NTHR, SMEM_BYTES>>>(x, wt, bs, out);
}

// round 7
// speedup vs baseline: 1.2448x; 1.2448x over previous
#include <cuda_runtime.h>
#include <cstdint>

// Problem constants (B=64, C=512, H=W=28, G=8)
#define HWN    784       // H*W
#define HW4    196       // HW/4
#define CPG    64        // channels per group
#define CPC    32        // channels per CTA (half group)
#define NCTA   1024      // 512 tiles x 2 CTAs
#define EPS    1e-5f
#define NTHR   256       // 8 warps

#define HALF_BYTES  (CPC * HWN * 4)     // 100352
#define CHUNK_BYTES (HALF_BYTES / 4)    // 25088

// smem layout (floats):
//   [0, CPC*HWN)   x half-tile (25088 floats)
//   + HWN          s partial / gate (784, float4-viewed)
//   + CPC          channel means (32)
//   + 20           reduction scratch (16 partials + mu + rsig)
//   + 2            mbarrier (u64, 8B aligned)
#define OFF_S     (CPC * HWN)
#define OFF_MEANS (OFF_S + HWN)
#define OFF_RED   (OFF_MEANS + CPC)
#define OFF_MBAR  (OFF_RED + 20)
#define SMEM_FLOATS (OFF_MBAR + 2)
#define SMEM_BYTES  (SMEM_FLOATS * 4)

__device__ __forceinline__ uint32_t smem_u32(const void* p) {
    uint32_t a;
    asm("{ .reg .u64 t; cvta.to.shared.u64 t, %1; cvt.u32.u64 %0, t; }"
        : "=r"(a) : "l"(p));
    return a;
}

__device__ __forceinline__ void cluster_sync_() {
    asm volatile("barrier.cluster.arrive.aligned;" ::: "memory");
    asm volatile("barrier.cluster.wait.aligned;" ::: "memory");
}

__global__ __launch_bounds__(NTHR, 2) __cluster_dims__(2, 1, 1)
void simam_cluster_kernel(const float* __restrict__ x,
                          const float* __restrict__ weight,
                          const float* __restrict__ bias,
                          float* __restrict__ out)
{
    extern __shared__ float smem[];
    float*  sx      = smem;
    float4* s_s4    = (float4*)(smem + OFF_S);      // 196 float4 partial s / gate
    float*  s_means = smem + OFF_MEANS;
    float*  s_red   = smem + OFF_RED;
    const uint32_t mbar = smem_u32(smem + OFF_MBAR);

    const int rank = (int)(blockIdx.x & 1);         // CTA rank in cluster
    const int bg   = (int)(blockIdx.x >> 1);        // tile id
    const int g    = bg & 7;
    const float* xt = x   + (size_t)bg * (CPG * HWN) + (size_t)rank * (CPC * HWN);
    float*       ot = out + (size_t)bg * (CPG * HWN) + (size_t)rank * (CPC * HWN);

    const int tid  = threadIdx.x;
    const int w    = tid >> 5;
    const int lane = tid & 31;

    // ---- TMA bulk load of this CTA's 32-channel half (contiguous 100 KB) ----
    if (tid == 0) {
        asm volatile("mbarrier.init.shared::cta.b64 [%0], 1;" :: "r"(mbar) : "memory");
    }
    __syncthreads();
    if (tid == 0) {
        asm volatile("mbarrier.arrive.expect_tx.shared::cta.b64 _, [%0], %1;"
                     :: "r"(mbar), "r"((uint32_t)HALF_BYTES) : "memory");
        const uint32_t dst0 = smem_u32(sx);
        #pragma unroll
        for (int i = 0; i < 4; i++) {
            asm volatile(
                "cp.async.bulk.shared::cluster.global.mbarrier::complete_tx::bytes "
                "[%0], [%1], %2, [%3];"
                :: "r"(dst0 + i * CHUNK_BYTES),
                   "l"((const char*)xt + i * CHUNK_BYTES),
                   "r"((uint32_t)CHUNK_BYTES),
                   "r"(mbar)
                : "memory");
        }
    }
    asm volatile(
        "{\n\t"
        ".reg .pred P;\n\t"
        "WL_%=: mbarrier.try_wait.parity.acquire.cta.shared::cta.b64 P, [%0], 0, 0x989680;\n\t"
        "@P bra WD_%=;\n\t"
        "bra WL_%=;\n\t"
        "WD_%=:\n\t"
        "}" :: "r"(mbar) : "memory");

    // ---- per-channel means: 8 warps x 4 channels ----
    #pragma unroll
    for (int i = 0; i < 4; i++) {
        const int c = w + 8 * i;
        const float4* row = (const float4*)(sx + c * HWN);
        float cs = 0.f;
        #pragma unroll
        for (int k = 0; k < 7; k++) {
            const int j = lane + 32 * k;
            if (j < HW4) {
                float4 v = row[j];
                cs += (v.x + v.y) + (v.z + v.w);
            }
        }
        #pragma unroll
        for (int o = 16; o; o >>= 1) cs += __shfl_xor_sync(0xffffffffu, cs, o);
        if (lane == 0) s_means[c] = cs * (1.0f / HWN);
    }
    __syncthreads();

    // ---- partial s over this CTA's 32 channels ----
    float4 acc = make_float4(0.f, 0.f, 0.f, 0.f);
    if (tid < HW4) {
        const float4* col = (const float4*)sx + tid;    // stride HW4 per channel
        #pragma unroll 8
        for (int c = 0; c < CPC; c++) {
            const float  m = s_means[c];
            const float4 v = col[c * HW4];
            acc.x += m * v.x;
            acc.y += m * v.y;
            acc.z += m * v.z;
            acc.w += m * v.w;
        }
        s_s4[tid] = acc;       // publish partial for peer
    }
    // both CTAs must have published partials before cross-reads
    cluster_sync_();

    // ---- fetch peer partial via DSMEM, form total s in registers ----
    float4 tot = acc;
    if (tid < HW4) {
        const uint32_t laddr = smem_u32(&s_s4[tid]);
        uint32_t raddr;
        asm("mapa.shared::cluster.u32 %0, %1, %2;"
            : "=r"(raddr) : "r"(laddr), "r"(rank ^ 1));
        float4 p;
        asm volatile("ld.shared::cluster.v4.f32 {%0,%1,%2,%3}, [%4];"
                     : "=f"(p.x), "=f"(p.y), "=f"(p.z), "=f"(p.w)
                     : "r"(raddr));
        tot.x += p.x; tot.y += p.y; tot.z += p.z; tot.w += p.w;
    }

    // ---- stats over total s (redundant in both CTAs, deterministic) ----
    float lsum = 0.f, lsq = 0.f;
    if (tid < HW4) {
        lsum = (tot.x + tot.y) + (tot.z + tot.w);
        lsq  = tot.x * tot.x + tot.y * tot.y + tot.z * tot.z + tot.w * tot.w;
    }
    #pragma unroll
    for (int o = 16; o; o >>= 1) {
        lsum += __shfl_xor_sync(0xffffffffu, lsum, o);
        lsq  += __shfl_xor_sync(0xffffffffu, lsq,  o);
    }
    if (lane == 0) { s_red[w] = lsum; s_red[8 + w] = lsq; }
    __syncthreads();
    if (tid == 0) {
        float ts = 0.f, tq = 0.f;
        #pragma unroll
        for (int i = 0; i < 8; i++) { ts += s_red[i]; tq += s_red[8 + i]; }
        const float mu  = ts * (1.0f / HWN);
        const float var = tq * (1.0f / HWN) - mu * mu;
        s_red[16] = mu;
        s_red[17] = rsqrtf(var + EPS);
    }
    // peer must finish reading our partial s before we overwrite it with gate
    cluster_sync_();

    // ---- gate written into s buffer ----
    {
        const float mu = s_red[16];
        const float rs = s_red[17];
        const float wg = weight[g];
        const float bb = bias[g];
        if (tid < HW4) {
            float4 gt;
            gt.x = 1.0f / (1.0f + __expf(-((tot.x - mu) * rs * wg + bb)));
            gt.y = 1.0f / (1.0f + __expf(-((tot.y - mu) * rs * wg + bb)));
            gt.z = 1.0f / (1.0f + __expf(-((tot.z - mu) * rs * wg + bb)));
            gt.w = 1.0f / (1.0f + __expf(-((tot.w - mu) * rs * wg + bb)));
            s_s4[tid] = gt;
        }
    }
    __syncthreads();

    // ---- multiply + store (smem read -> STG, fire-and-forget) ----
    #pragma unroll
    for (int i = 0; i < 4; i++) {
        const int c = w + 8 * i;
        const float4* srow = (const float4*)(sx + c * HWN);
        float4*       orow = (float4*)(ot + c * HWN);
        #pragma unroll
        for (int k = 0; k < 7; k++) {
            const int j = lane + 32 * k;
            if (j < HW4) {
                float4 v  = srow[j];
                float4 gt = s_s4[j];
                v.x *= gt.x; v.y *= gt.y; v.z *= gt.z; v.w *= gt.w;
                orow[j] = v;
            }
        }
    }
}

extern "C" void kernel_launch(void* const* d_in, const int* in_sizes, int n_in,
                              void* d_out, int out_size)
{
    const float* x  = (const float*)d_in[0];
    const float* wt = (const float*)d_in[1];
    const float* bs = (const float*)d_in[2];
    float* out = (float*)d_out;

    cudaFuncSetAttribute(simam_cluster_kernel,
                         cudaFuncAttributeMaxDynamicSharedMemorySize, SMEM_BYTES);
    simam_cluster_kernel<<<NCTA, NTHR, SMEM_BYTES>>>(x, wt, bs, out);
}